// round 2
// baseline (speedup 1.0000x reference)
#include <cuda_runtime.h>
#include <math.h>

#define BB 64
#define NNODES 128
#define HH 32
#define HEc 64
#define OEc 32
#define NT (BB*NNODES)
#define ALPHA 0.1f
#define BNEPS 1e-5f

static const double NE_D = 1048576.0;  // B*N*N edges
static const double NT_D = 8192.0;     // B*N nodes

// ----------------- device scratch (no allocs allowed) -----------------
__device__ __align__(16) float g_x[NT*HH];
__device__ __align__(16) float g_Q1[NT*HEc];
__device__ __align__(16) float g_P2[NT*HEc];
__device__ __align__(16) float g_Sagg[NT*OEc];
__device__ __align__(16) float g_h1[NT*HH];
__device__ __align__(16) float g_h2[NT*HH];
__device__ double g_su[HEc],  g_ssu[HEc];
__device__ double g_sv[OEc],  g_ssv[OEc];
__device__ double g_sh0[HH],  g_ssh0[HH];
__device__ double g_sh1[HH],  g_ssh1[HH];
__device__ __align__(16) float g_Waf[HEc*OEc];
__device__ __align__(16) float g_baf[OEc];

__device__ __forceinline__ float lrelu(float z){ return fmaxf(z, ALPHA*z); }

// ----------------------------------------------------------------------
__global__ void k_zero(){
    int t = threadIdx.x;
    if (t < HEc){ g_su[t]=0.0; g_ssu[t]=0.0; }
    if (t < OEc){ g_sv[t]=0.0; g_ssv[t]=0.0; }
    if (t < HH){ g_sh0[t]=0.0; g_ssh0[t]=0.0; g_sh1[t]=0.0; g_ssh1[t]=0.0; }
}

__global__ void k_pad(const float* __restrict__ xin){
    int i = blockIdx.x*256 + threadIdx.x;
    if (i < NT*HH){
        int node = i >> 5, k = i & 31;
        g_x[i] = (k < 3) ? xin[node*3 + k] : 0.0f;
    }
}

// Q1 = x@Wah[0:32] + bah ; P2 = x@Wah[32:64]
__global__ void __launch_bounds__(256) k_pre(const float* __restrict__ Wah_i,
                                             const float* __restrict__ bah_i){
    __shared__ float xs[64*33];
    __shared__ float W1s[32*64];
    __shared__ float W2s[32*64];
    __shared__ float bs[64];
    int t = threadIdx.x;
    int n0 = blockIdx.x*64;
    for (int idx=t; idx<64*32; idx+=256){
        int n = idx>>5, k = idx&31;
        xs[n*33+k] = g_x[(n0+n)*32 + k];
    }
    for (int idx=t; idx<32*64; idx+=256){
        int k = idx>>6, c = idx&63;
        W1s[idx] = Wah_i[k*64 + c];
        W2s[idx] = Wah_i[(32+k)*64 + c];
    }
    if (t < 64) bs[t] = bah_i[t];
    __syncthreads();
    int c = t & 63, ng = t >> 6;
    for (int n=ng; n<64; n+=4){
        float q = bs[c], p = 0.0f;
        #pragma unroll
        for (int k=0;k<32;k++){
            float xv = xs[n*33+k];
            q = fmaf(xv, W1s[k*64+c], q);
            p = fmaf(xv, W2s[k*64+c], p);
        }
        g_Q1[(n0+n)*64 + c] = q;
        g_P2[(n0+n)*64 + c] = p;
    }
}

// ---------------- edge pass 1: stats of u = lrelu(z1) -----------------
__global__ void __launch_bounds__(256) k_edge_stats(const float* __restrict__ Wah_i){
    extern __shared__ float sm[];
    float* P2r = sm;               // 8192
    float* xr  = P2r + 8192;       // 4224
    float* xa  = xr  + 4224;       // 528
    float* Q1a = xa  + 528;        // 1024
    float* wd  = Q1a + 1024;       // 64
    float* wi  = wd  + 64;         // 64
    float* db  = wi  + 64;         // 128
    float* ib  = db  + 128;        // 128
    float* red = ib  + 128;        // 256

    int t = threadIdx.x;
    int b = blockIdx.y;
    int a0 = blockIdx.x*16;

    for (int idx=t; idx<8192; idx+=256) P2r[idx] = g_P2[b*8192 + idx];
    for (int idx=t; idx<4096; idx+=256){
        int r = idx>>5, k = idx&31;
        xr[r*33+k] = g_x[b*4096 + idx];
    }
    for (int idx=t; idx<512; idx+=256){
        int n = idx>>5, k = idx&31;
        xa[n*33+k] = g_x[(b*128 + a0 + n)*32 + k];
    }
    for (int idx=t; idx<1024; idx+=256) Q1a[idx] = g_Q1[(b*128+a0)*64 + idx];
    if (t < 64){ wd[t] = Wah_i[64*64 + t]; wi[t] = Wah_i[65*64 + t]; }
    __syncthreads();

    int k = t & 63, g = t >> 6;
    float wdk = wd[k], wik = wi[k];
    float su = 0.0f, ssu = 0.0f;

    for (int as=0; as<16; as++){
        if (t < 128){
            float s = 0.0f;
            #pragma unroll
            for (int kk=0;kk<31;kk++){
                float df = xr[t*33+kk] - xa[as*33+kk] + 1e-12f;
                s = fmaf(df, df, s);
            }
            db[t] = sqrtf(s);
            ib[t] = 1.0f - (xr[t*33+31] - xa[as*33+31]);
        }
        __syncthreads();
        float q = Q1a[as*64 + k];
        #pragma unroll 4
        for (int p=g; p<128; p+=4){
            float z = q + P2r[p*64+k] + db[p]*wdk + ib[p]*wik;
            float u = lrelu(z);
            su += u; ssu = fmaf(u,u,ssu);
        }
        __syncthreads();
    }
    red[g*64+k] = su;
    __syncthreads();
    if (g == 0){
        double s4 = (double)red[k] + (double)red[64+k] + (double)red[128+k] + (double)red[192+k];
        atomicAdd(&g_su[k], s4);
    }
    __syncthreads();
    red[g*64+k] = ssu;
    __syncthreads();
    if (g == 0){
        double s4 = (double)red[k] + (double)red[64+k] + (double)red[128+k] + (double)red[192+k];
        atomicAdd(&g_ssu[k], s4);
    }
}

// ---------------- fold BN1 into GEMM2 ----------------------------------
__global__ void k_fold1(const float* __restrict__ Wa_i, const float* __restrict__ ba_i,
                        const float* __restrict__ geh,  const float* __restrict__ beh){
    __shared__ float s1[64], t1[64];
    int t = threadIdx.x;
    if (t < 64){
        double m = g_su[t]/NE_D;
        double v = g_ssu[t]/NE_D - m*m;
        float s = geh[t] * rsqrtf((float)v + BNEPS);
        s1[t] = s; t1[t] = beh[t] - (float)m*s;
    }
    __syncthreads();
    for (int idx=t; idx<64*32; idx+=256){
        int k = idx>>5;
        g_Waf[idx] = s1[k]*Wa_i[idx];
    }
    if (t < 32){
        float acc = ba_i[t];
        #pragma unroll
        for (int k=0;k<64;k++) acc = fmaf(t1[k], Wa_i[k*32+t], acc);
        g_baf[t] = acc;
    }
}

// ---------------- edge pass 2: main (GEMM2 + aggregate + v-stats) -----
__global__ void __launch_bounds__(256) k_edge_main(const float* __restrict__ Wah_i){
    extern __shared__ float sm[];
    float* P2r = sm;               // 8192
    float* us  = P2r + 8192;       // 8192
    float* xr  = us  + 8192;       // 4224
    float* xa  = xr  + 4224;       // 528
    float* Q1a = xa  + 528;        // 1024
    float* wd  = Q1a + 1024;       // 64
    float* wi  = wd  + 64;         // 64
    float* db  = wi  + 64;         // 128
    float* ib  = db  + 128;        // 128
    float* bafs= ib  + 128;        // 32
    float* red2= bafs+ 32;         // 256

    int t = threadIdx.x;
    int b = blockIdx.y;
    int a0 = blockIdx.x*16;

    for (int idx=t; idx<8192; idx+=256) P2r[idx] = g_P2[b*8192 + idx];
    for (int idx=t; idx<4096; idx+=256){
        int r = idx>>5, k = idx&31;
        xr[r*33+k] = g_x[b*4096 + idx];
    }
    for (int idx=t; idx<512; idx+=256){
        int n = idx>>5, k = idx&31;
        xa[n*33+k] = g_x[(b*128 + a0 + n)*32 + k];
    }
    for (int idx=t; idx<1024; idx+=256) Q1a[idx] = g_Q1[(b*128+a0)*64 + idx];
    if (t < 64){ wd[t] = Wah_i[64*64 + t]; wi[t] = Wah_i[65*64 + t]; }
    if (t < 32){ bafs[t] = g_baf[t]; }

    // per-thread weight column for the 64x32 GEMM
    int c  = t & 31, gy = t >> 5;   // GEMM layout: 8 groups x 32 channels
    int k  = t & 63, gu = t >> 6;   // u-compute layout: 4 groups x 64 channels
    float wcol[64];
    #pragma unroll
    for (int kk=0;kk<64;kk++) wcol[kk] = g_Waf[kk*32 + c];
    __syncthreads();

    float ssv = 0.0f;

    for (int as=0; as<16; as++){
        if (t < 128){
            float s = 0.0f;
            #pragma unroll
            for (int kk=0;kk<31;kk++){
                float df = xr[t*33+kk] - xa[as*33+kk] + 1e-12f;
                s = fmaf(df, df, s);
            }
            db[t] = sqrtf(s);
            ib[t] = 1.0f - (xr[t*33+31] - xa[as*33+31]);
        }
        __syncthreads();

        // u-compute into shared
        {
            float q = Q1a[as*64 + k];
            float wdk = wd[k], wik = wi[k];
            #pragma unroll 4
            for (int p=gu; p<128; p+=4){
                float z = q + P2r[p*64+k] + db[p]*wdk + ib[p]*wik;
                us[p*64+k] = lrelu(z);
            }
        }
        __syncthreads();

        // GEMM: y[c] for 16 edges per thread; aggregate over receivers
        float vsum = 0.0f;
        for (int p=gy; p<128; p+=8){
            const float4* up = reinterpret_cast<const float4*>(us + p*64);
            float y = bafs[c];
            #pragma unroll
            for (int k4=0;k4<16;k4++){
                float4 u4 = up[k4];
                y = fmaf(u4.x, wcol[4*k4+0], y);
                y = fmaf(u4.y, wcol[4*k4+1], y);
                y = fmaf(u4.z, wcol[4*k4+2], y);
                y = fmaf(u4.w, wcol[4*k4+3], y);
            }
            float v = lrelu(y);
            vsum += v;
            ssv = fmaf(v, v, ssv);
        }
        red2[gy*32 + c] = vsum;
        __syncthreads();
        if (t < 32){
            float s = 0.0f;
            #pragma unroll
            for (int j=0;j<8;j++) s += red2[j*32 + t];
            g_Sagg[(b*128 + a0 + as)*32 + t] = s;
        }
        __syncthreads();
    }

    // reduce ssv across block -> global
    red2[gy*32 + c] = ssv;
    __syncthreads();
    if (t < 32){
        float s = 0.0f;
        #pragma unroll
        for (int j=0;j<8;j++) s += red2[j*32 + t];
        atomicAdd(&g_ssv[t], (double)s);
    }
}

// ---------------- sum of v per channel (from Sagg) ---------------------
__global__ void __launch_bounds__(256) k_sumv(){
    __shared__ float red[256];
    int t = threadIdx.x;
    int c = t & 31, rg = t >> 5;
    int base = blockIdx.x*256;
    float s = 0.0f;
    for (int r = base + rg; r < base + 256; r += 8) s += g_Sagg[r*32 + c];
    red[rg*32 + c] = s;
    __syncthreads();
    if (t < 32){
        float acc = 0.0f;
        #pragma unroll
        for (int j=0;j<8;j++) acc += red[j*32 + t];
        atomicAdd(&g_sv[t], (double)acc);
    }
}

// ---------------- node layer 0 -----------------------------------------
__global__ void __launch_bounds__(256) k_node0(const float* __restrict__ Wn0_i,
                                               const float* __restrict__ bn0_i,
                                               const float* __restrict__ ge_i,
                                               const float* __restrict__ be_i){
    __shared__ float W[2048];
    __shared__ float s2[32], t2[32], bsh[32], ssum[32], sssum[32];
    int t = threadIdx.x;
    if (t < 32){
        double m = g_sv[t]/NE_D;
        double v = g_ssv[t]/NE_D - m*m;
        float s = ge_i[t] * rsqrtf((float)v + BNEPS);
        s2[t] = s; t2[t] = be_i[t] - (float)m*s;
        bsh[t] = bn0_i[t]; ssum[t] = 0.0f; sssum[t] = 0.0f;
    }
    for (int idx=t; idx<2048; idx+=256) W[idx] = Wn0_i[idx];
    __syncthreads();

    int row = blockIdx.x*256 + t;
    float in[64];
    #pragma unroll
    for (int cc=0;cc<32;cc++){
        in[cc]    = fmaf(s2[cc], g_Sagg[row*32+cc], 128.0f*t2[cc]);
        in[32+cc] = g_x[row*32+cc];
    }
    float z[32];
    #pragma unroll
    for (int cc=0;cc<32;cc++) z[cc] = bsh[cc];
    #pragma unroll
    for (int kk=0;kk<64;kk++){
        float xv = in[kk];
        #pragma unroll
        for (int cc=0;cc<32;cc++) z[cc] = fmaf(xv, W[kk*32+cc], z[cc]);
    }
    int lane = t & 31;
    #pragma unroll
    for (int cc=0;cc<32;cc++){
        float h = lrelu(z[cc]);
        g_h1[row*32+cc] = h;
        float v1 = h, v2 = h*h;
        #pragma unroll
        for (int off=16; off>0; off>>=1){
            v1 += __shfl_xor_sync(0xFFFFFFFFu, v1, off);
            v2 += __shfl_xor_sync(0xFFFFFFFFu, v2, off);
        }
        if (lane == 0){ atomicAdd(&ssum[cc], v1); atomicAdd(&sssum[cc], v2); }
    }
    __syncthreads();
    if (t < 32){
        atomicAdd(&g_sh0[t], (double)ssum[t]);
        atomicAdd(&g_ssh0[t], (double)sssum[t]);
    }
}

// ---------------- node layer 1 -----------------------------------------
__global__ void __launch_bounds__(256) k_node1(const float* __restrict__ Wn_i,
                                               const float* __restrict__ bnn_i,
                                               const float* __restrict__ gn0,
                                               const float* __restrict__ bn0v){
    __shared__ float W[1024];
    __shared__ float s0[32], t0[32], bsh[32], ssum[32], sssum[32];
    int t = threadIdx.x;
    if (t < 32){
        double m = g_sh0[t]/NT_D;
        double v = g_ssh0[t]/NT_D - m*m;
        float s = gn0[t] * rsqrtf((float)v + BNEPS);
        s0[t] = s; t0[t] = bn0v[t] - (float)m*s;
        bsh[t] = bnn_i[t]; ssum[t] = 0.0f; sssum[t] = 0.0f;
    }
    for (int idx=t; idx<1024; idx+=256) W[idx] = Wn_i[idx];
    __syncthreads();

    int row = blockIdx.x*256 + t;
    float hn[32];
    #pragma unroll
    for (int kk=0;kk<32;kk++) hn[kk] = fmaf(s0[kk], g_h1[row*32+kk], t0[kk]);
    float z[32];
    #pragma unroll
    for (int cc=0;cc<32;cc++) z[cc] = bsh[cc];
    #pragma unroll
    for (int kk=0;kk<32;kk++){
        float xv = hn[kk];
        #pragma unroll
        for (int cc=0;cc<32;cc++) z[cc] = fmaf(xv, W[kk*32+cc], z[cc]);
    }
    int lane = t & 31;
    #pragma unroll
    for (int cc=0;cc<32;cc++){
        float h = lrelu(z[cc]);
        g_h2[row*32+cc] = h;
        float v1 = h, v2 = h*h;
        #pragma unroll
        for (int off=16; off>0; off>>=1){
            v1 += __shfl_xor_sync(0xFFFFFFFFu, v1, off);
            v2 += __shfl_xor_sync(0xFFFFFFFFu, v2, off);
        }
        if (lane == 0){ atomicAdd(&ssum[cc], v1); atomicAdd(&sssum[cc], v2); }
    }
    __syncthreads();
    if (t < 32){
        atomicAdd(&g_sh1[t], (double)ssum[t]);
        atomicAdd(&g_ssh1[t], (double)sssum[t]);
    }
}

// ---------------- node final: update linear + tanh ---------------------
__global__ void __launch_bounds__(256) k_node2(const float* __restrict__ Wu_i,
                                               const float* __restrict__ bu_i,
                                               const float* __restrict__ gn1,
                                               const float* __restrict__ bn1v,
                                               float* __restrict__ out,
                                               int is_last){
    __shared__ float W[1024];
    __shared__ float s0[32], t0[32], bsh[32];
    int t = threadIdx.x;
    if (t < 32){
        double m = g_sh1[t]/NT_D;
        double v = g_ssh1[t]/NT_D - m*m;
        float s = gn1[t] * rsqrtf((float)v + BNEPS);
        s0[t] = s; t0[t] = bn1v[t] - (float)m*s;
        bsh[t] = bu_i[t];
    }
    for (int idx=t; idx<1024; idx+=256) W[idx] = Wu_i[idx];
    __syncthreads();

    int row = blockIdx.x*256 + t;
    float hn[32];
    #pragma unroll
    for (int kk=0;kk<32;kk++) hn[kk] = fmaf(s0[kk], g_h2[row*32+kk], t0[kk]);
    float z[32];
    #pragma unroll
    for (int cc=0;cc<32;cc++) z[cc] = bsh[cc];
    #pragma unroll
    for (int kk=0;kk<32;kk++){
        float xv = hn[kk];
        #pragma unroll
        for (int cc=0;cc<32;cc++) z[cc] = fmaf(xv, W[kk*32+cc], z[cc]);
    }
    #pragma unroll
    for (int cc=0;cc<32;cc++){
        float o = tanhf(z[cc]);
        g_x[row*32+cc] = o;
        if (is_last) out[row*32+cc] = o;
    }
}

// ----------------------------------------------------------------------
extern "C" void kernel_launch(void* const* d_in, const int* in_sizes, int n_in,
                              void* d_out, int out_size){
    const float* x    = (const float*)d_in[0];
    const float* Wah  = (const float*)d_in[1];
    const float* bah  = (const float*)d_in[2];
    const float* Wa   = (const float*)d_in[3];
    const float* ba   = (const float*)d_in[4];
    const float* geh  = (const float*)d_in[5];
    const float* beh  = (const float*)d_in[6];
    const float* ge   = (const float*)d_in[7];
    const float* be   = (const float*)d_in[8];
    const float* Wn0  = (const float*)d_in[9];
    const float* bn0  = (const float*)d_in[10];
    const float* Wn   = (const float*)d_in[11];
    const float* bnn  = (const float*)d_in[12];
    const float* gn   = (const float*)d_in[13];
    const float* bnv  = (const float*)d_in[14];
    const float* Wu   = (const float*)d_in[15];
    const float* bu   = (const float*)d_in[16];
    float* out = (float*)d_out;

    const size_t SMEM_STATS = (8192+4224+528+1024+64+64+128+128+256)*sizeof(float);
    const size_t SMEM_MAIN  = (8192+8192+4224+528+1024+64+64+128+128+32+256)*sizeof(float);
    cudaFuncSetAttribute(k_edge_stats, cudaFuncAttributeMaxDynamicSharedMemorySize, (int)SMEM_STATS);
    cudaFuncSetAttribute(k_edge_main,  cudaFuncAttributeMaxDynamicSharedMemorySize, (int)SMEM_MAIN);

    k_pad<<<NT*HH/256, 256>>>(x);

    for (int i=0; i<4; i++){
        k_zero<<<1,128>>>();
        k_pre<<<128,256>>>(Wah + i*66*64, bah + i*64);
        k_edge_stats<<<dim3(8,64),256,SMEM_STATS>>>(Wah + i*66*64);
        k_fold1<<<1,256>>>(Wa + i*64*32, ba + i*32, geh + i*64, beh + i*64);
        k_edge_main<<<dim3(8,64),256,SMEM_MAIN>>>(Wah + i*66*64);
        k_sumv<<<32,256>>>();
        k_node0<<<32,256>>>(Wn0 + i*64*32, bn0 + i*32, ge + i*32, be + i*32);
        k_node1<<<32,256>>>(Wn + i*32*32, bnn + i*32, gn + (i*2+0)*32, bnv + (i*2+0)*32);
        k_node2<<<32,256>>>(Wu + i*32*32, bu + i*32, gn + (i*2+1)*32, bnv + (i*2+1)*32,
                            out, (i==3) ? 1 : 0);
    }
}

// round 3
// speedup vs baseline: 1.0564x; 1.0564x over previous
#include <cuda_runtime.h>
#include <math.h>

#define BB 64
#define NNODES 128
#define HH 32
#define HEc 64
#define OEc 32
#define NT (BB*NNODES)
#define ALPHA 0.1f
#define BNEPS 1e-5f

static const double NE_D = 1048576.0;  // B*N*N edges
static const double NT_D = 8192.0;     // B*N nodes

// ----------------- device scratch (no allocs allowed) -----------------
__device__ __align__(16) float g_x[NT*HH];
__device__ __align__(16) float g_Q1[NT*HEc];
__device__ __align__(16) float g_P2[NT*HEc];
__device__ __align__(16) float g_Sagg[NT*OEc];
__device__ __align__(16) float g_h1[NT*HH];
__device__ __align__(16) float g_h2[NT*HH];
__device__ double g_su[HEc],  g_ssu[HEc];
__device__ double g_sv[OEc],  g_ssv[OEc];
__device__ double g_sh0[HH],  g_ssh0[HH];
__device__ double g_sh1[HH],  g_ssh1[HH];
__device__ __align__(16) float g_Waf[HEc*OEc];
__device__ __align__(16) float g_baf[OEc];

__device__ __forceinline__ float lrelu(float z){ return fmaxf(z, ALPHA*z); }

// ----------------------------------------------------------------------
__global__ void k_zero(){
    int t = threadIdx.x;
    if (t < HEc){ g_su[t]=0.0; g_ssu[t]=0.0; }
    if (t < OEc){ g_sv[t]=0.0; g_ssv[t]=0.0; }
    if (t < HH){ g_sh0[t]=0.0; g_ssh0[t]=0.0; g_sh1[t]=0.0; g_ssh1[t]=0.0; }
}

__global__ void k_pad(const float* __restrict__ xin){
    int i = blockIdx.x*256 + threadIdx.x;
    if (i < NT*HH){
        int node = i >> 5, k = i & 31;
        g_x[i] = (k < 3) ? xin[node*3 + k] : 0.0f;
    }
}

// Q1 = x@Wah[0:32] + bah ; P2 = x@Wah[32:64]
__global__ void __launch_bounds__(256) k_pre(const float* __restrict__ Wah_i,
                                             const float* __restrict__ bah_i){
    __shared__ float xs[64*33];
    __shared__ float W1s[32*64];
    __shared__ float W2s[32*64];
    __shared__ float bs[64];
    int t = threadIdx.x;
    int n0 = blockIdx.x*64;
    for (int idx=t; idx<64*32; idx+=256){
        int n = idx>>5, k = idx&31;
        xs[n*33+k] = g_x[(n0+n)*32 + k];
    }
    for (int idx=t; idx<32*64; idx+=256){
        int k = idx>>6, c = idx&63;
        W1s[idx] = Wah_i[k*64 + c];
        W2s[idx] = Wah_i[(32+k)*64 + c];
    }
    if (t < 64) bs[t] = bah_i[t];
    __syncthreads();
    int c = t & 63, ng = t >> 6;
    for (int n=ng; n<64; n+=4){
        float q = bs[c], p = 0.0f;
        #pragma unroll
        for (int k=0;k<32;k++){
            float xv = xs[n*33+k];
            q = fmaf(xv, W1s[k*64+c], q);
            p = fmaf(xv, W2s[k*64+c], p);
        }
        g_Q1[(n0+n)*64 + c] = q;
        g_P2[(n0+n)*64 + c] = p;
    }
}

// ---------------- edge pass 1: stats of u = lrelu(z1) -----------------
__global__ void __launch_bounds__(256) k_edge_stats(const float* __restrict__ Wah_i){
    extern __shared__ float sm[];
    float*  P2r = sm;                       // 8192
    float*  xr  = P2r + 8192;               // 128*33 = 4224
    float2* de  = (float2*)(xr + 4224);     // 2048 float2
    float*  red = (float*)(de + 2048);      // 256

    int t  = threadIdx.x;
    int b  = blockIdx.y;
    int a0 = blockIdx.x*16;

    for (int idx=t; idx<2048; idx+=256)
        ((float4*)P2r)[idx] = ((const float4*)(g_P2 + b*8192))[idx];
    for (int idx=t; idx<4096; idx+=256){
        int r = idx>>5, kk = idx&31;
        xr[r*33+kk] = g_x[b*4096 + idx];
    }
    __syncthreads();

    // all (as, p) distance pairs up-front
    #pragma unroll
    for (int j=0;j<8;j++){
        int e  = t + 256*j;
        int as = e >> 7, p = e & 127;
        const float* xra = xr + (a0+as)*33;
        const float* xrp = xr + p*33;
        float s = 0.0f;
        #pragma unroll
        for (int kk=0;kk<31;kk++){
            float df = xrp[kk] - xra[kk] + 1e-12f;
            s = fmaf(df, df, s);
        }
        de[e] = make_float2(sqrtf(s), 1.0f - (xrp[31]-xra[31]));
    }
    __syncthreads();

    int k = t & 63, g = t >> 6;
    float wdk = Wah_i[64*64 + k];
    float wik = Wah_i[65*64 + k];
    float q[16];
    #pragma unroll
    for (int as=0; as<16; as++) q[as] = g_Q1[(b*128+a0+as)*64 + k];

    float su = 0.0f, ssu = 0.0f;
    for (int p=g; p<128; p+=4){
        float pv = P2r[p*64+k];
        #pragma unroll
        for (int as=0; as<16; as++){
            float2 e2 = de[as*128+p];
            float z = fmaf(e2.x, wdk, q[as] + pv);
            z = fmaf(e2.y, wik, z);
            float u = fmaxf(z, ALPHA*z);
            su += u; ssu = fmaf(u,u,ssu);
        }
    }
    red[g*64+k] = su;
    __syncthreads();
    if (g == 0)
        atomicAdd(&g_su[k], (double)(red[k]+red[64+k]+red[128+k]+red[192+k]));
    __syncthreads();
    red[g*64+k] = ssu;
    __syncthreads();
    if (g == 0)
        atomicAdd(&g_ssu[k], (double)(red[k]+red[64+k]+red[128+k]+red[192+k]));
}

// ---------------- fold BN1 into GEMM2 ----------------------------------
__global__ void k_fold1(const float* __restrict__ Wa_i, const float* __restrict__ ba_i,
                        const float* __restrict__ geh,  const float* __restrict__ beh){
    __shared__ float s1[64], t1[64];
    int t = threadIdx.x;
    if (t < 64){
        double m = g_su[t]/NE_D;
        double v = g_ssu[t]/NE_D - m*m;
        float s = geh[t] * rsqrtf((float)v + BNEPS);
        s1[t] = s; t1[t] = beh[t] - (float)m*s;
    }
    __syncthreads();
    for (int idx=t; idx<64*32; idx+=256){
        int k = idx>>5;
        g_Waf[idx] = s1[k]*Wa_i[idx];
    }
    if (t < 32){
        float acc = ba_i[t];
        #pragma unroll
        for (int k=0;k<64;k++) acc = fmaf(t1[k], Wa_i[k*32+t], acc);
        g_baf[t] = acc;
    }
}

// ---------------- edge pass 2: main (GEMM2 + aggregate + v-stats + sumv)
__global__ void __launch_bounds__(256) k_edge_main(const float* __restrict__ Wah_i){
    extern __shared__ float sm[];
    float*  P2r  = sm;                      // 8192
    float*  us   = P2r + 8192;              // 8192 (xr aliases the front)
    float*  xr   = us;                      // 4224 transient
    float2* de   = (float2*)(us + 8192);    // 2048 float2
    float*  red2 = (float*)(de + 2048);     // 256
    float*  bafs = red2 + 256;              // 32

    int t  = threadIdx.x;
    int b  = blockIdx.y;
    int a0 = blockIdx.x*16;

    for (int idx=t; idx<2048; idx+=256)
        ((float4*)P2r)[idx] = ((const float4*)(g_P2 + b*8192))[idx];
    for (int idx=t; idx<4096; idx+=256){
        int r = idx>>5, kk = idx&31;
        xr[r*33+kk] = g_x[b*4096 + idx];
    }
    if (t < 32) bafs[t] = g_baf[t];
    __syncthreads();

    #pragma unroll
    for (int j=0;j<8;j++){
        int e  = t + 256*j;
        int as = e >> 7, p = e & 127;
        const float* xra = xr + (a0+as)*33;
        const float* xrp = xr + p*33;
        float s = 0.0f;
        #pragma unroll
        for (int kk=0;kk<31;kk++){
            float df = xrp[kk] - xra[kk] + 1e-12f;
            s = fmaf(df, df, s);
        }
        de[e] = make_float2(sqrtf(s), 1.0f - (xrp[31]-xra[31]));
    }
    __syncthreads();   // after this, xr region is dead; us may overwrite

    int k  = t & 63, gu = t >> 6;          // u-compute layout
    int c  = t & 31, gy = t >> 5;          // GEMM layout
    float wdk = Wah_i[64*64 + k];
    float wik = Wah_i[65*64 + k];
    float q[16];
    #pragma unroll
    for (int as=0; as<16; as++) q[as] = g_Q1[(b*128+a0+as)*64 + k];
    float wcol[64];
    #pragma unroll
    for (int kk=0;kk<64;kk++) wcol[kk] = g_Waf[kk*32 + c];

    float ssv = 0.0f;
    float vtot = 0.0f;   // maintained by t<32

    for (int as=0; as<16; as++){
        // phase A: u into shared (all 256 threads)
        {
            float qa = q[as];
            #pragma unroll 4
            for (int p=gu; p<128; p+=4){
                float2 e2 = de[as*128+p];
                float z = fmaf(e2.x, wdk, qa + P2r[p*64+k]);
                z = fmaf(e2.y, wik, z);
                us[p*64+k] = fmaxf(z, ALPHA*z);
            }
        }
        __syncthreads();

        // phase B: 64x32 GEMM, 16 edges per thread, 4 accumulator chains
        float vsum = 0.0f;
        for (int p=gy; p<128; p+=8){
            const float4* up = reinterpret_cast<const float4*>(us + p*64);
            float ya = bafs[c], yb = 0.0f, yc = 0.0f, yd = 0.0f;
            #pragma unroll
            for (int k4=0;k4<16;k4+=4){
                float4 u0 = up[k4+0];
                ya = fmaf(u0.x, wcol[4*k4+ 0], ya); ya = fmaf(u0.y, wcol[4*k4+ 1], ya);
                ya = fmaf(u0.z, wcol[4*k4+ 2], ya); ya = fmaf(u0.w, wcol[4*k4+ 3], ya);
                float4 u1 = up[k4+1];
                yb = fmaf(u1.x, wcol[4*k4+ 4], yb); yb = fmaf(u1.y, wcol[4*k4+ 5], yb);
                yb = fmaf(u1.z, wcol[4*k4+ 6], yb); yb = fmaf(u1.w, wcol[4*k4+ 7], yb);
                float4 u2 = up[k4+2];
                yc = fmaf(u2.x, wcol[4*k4+ 8], yc); yc = fmaf(u2.y, wcol[4*k4+ 9], yc);
                yc = fmaf(u2.z, wcol[4*k4+10], yc); yc = fmaf(u2.w, wcol[4*k4+11], yc);
                float4 u3 = up[k4+3];
                yd = fmaf(u3.x, wcol[4*k4+12], yd); yd = fmaf(u3.y, wcol[4*k4+13], yd);
                yd = fmaf(u3.z, wcol[4*k4+14], yd); yd = fmaf(u3.w, wcol[4*k4+15], yd);
            }
            float y = (ya+yb)+(yc+yd);
            float v = fmaxf(y, ALPHA*y);
            vsum += v;
            ssv = fmaf(v, v, ssv);
        }
        red2[gy*32 + c] = vsum;
        __syncthreads();
        if (t < 32){
            float s = 0.0f;
            #pragma unroll
            for (int j=0;j<8;j++) s += red2[j*32 + t];
            g_Sagg[(b*128 + a0 + as)*32 + t] = s;
            vtot += s;
        }
        __syncthreads();
    }

    red2[gy*32 + c] = ssv;
    __syncthreads();
    if (t < 32){
        float s = 0.0f;
        #pragma unroll
        for (int j=0;j<8;j++) s += red2[j*32 + t];
        atomicAdd(&g_ssv[t], (double)s);
        atomicAdd(&g_sv[t],  (double)vtot);
    }
}

// ---------------- node layer 0 -----------------------------------------
__global__ void __launch_bounds__(256) k_node0(const float* __restrict__ Wn0_i,
                                               const float* __restrict__ bn0_i,
                                               const float* __restrict__ ge_i,
                                               const float* __restrict__ be_i){
    __shared__ float W[2048];
    __shared__ float s2[32], t2[32], bsh[32], ssum[32], sssum[32];
    int t = threadIdx.x;
    if (t < 32){
        double m = g_sv[t]/NE_D;
        double v = g_ssv[t]/NE_D - m*m;
        float s = ge_i[t] * rsqrtf((float)v + BNEPS);
        s2[t] = s; t2[t] = be_i[t] - (float)m*s;
        bsh[t] = bn0_i[t]; ssum[t] = 0.0f; sssum[t] = 0.0f;
    }
    for (int idx=t; idx<2048; idx+=256) W[idx] = Wn0_i[idx];
    __syncthreads();

    int row = blockIdx.x*256 + t;
    float in[64];
    #pragma unroll
    for (int cc=0;cc<32;cc++){
        in[cc]    = fmaf(s2[cc], g_Sagg[row*32+cc], 128.0f*t2[cc]);
        in[32+cc] = g_x[row*32+cc];
    }
    float z[32];
    #pragma unroll
    for (int cc=0;cc<32;cc++) z[cc] = bsh[cc];
    #pragma unroll
    for (int kk=0;kk<64;kk++){
        float xv = in[kk];
        #pragma unroll
        for (int cc=0;cc<32;cc++) z[cc] = fmaf(xv, W[kk*32+cc], z[cc]);
    }
    int lane = t & 31;
    #pragma unroll
    for (int cc=0;cc<32;cc++){
        float h = lrelu(z[cc]);
        g_h1[row*32+cc] = h;
        float v1 = h, v2 = h*h;
        #pragma unroll
        for (int off=16; off>0; off>>=1){
            v1 += __shfl_xor_sync(0xFFFFFFFFu, v1, off);
            v2 += __shfl_xor_sync(0xFFFFFFFFu, v2, off);
        }
        if (lane == 0){ atomicAdd(&ssum[cc], v1); atomicAdd(&sssum[cc], v2); }
    }
    __syncthreads();
    if (t < 32){
        atomicAdd(&g_sh0[t], (double)ssum[t]);
        atomicAdd(&g_ssh0[t], (double)sssum[t]);
    }
}

// ---------------- node layer 1 -----------------------------------------
__global__ void __launch_bounds__(256) k_node1(const float* __restrict__ Wn_i,
                                               const float* __restrict__ bnn_i,
                                               const float* __restrict__ gn0,
                                               const float* __restrict__ bn0v){
    __shared__ float W[1024];
    __shared__ float s0[32], t0[32], bsh[32], ssum[32], sssum[32];
    int t = threadIdx.x;
    if (t < 32){
        double m = g_sh0[t]/NT_D;
        double v = g_ssh0[t]/NT_D - m*m;
        float s = gn0[t] * rsqrtf((float)v + BNEPS);
        s0[t] = s; t0[t] = bn0v[t] - (float)m*s;
        bsh[t] = bnn_i[t]; ssum[t] = 0.0f; sssum[t] = 0.0f;
    }
    for (int idx=t; idx<1024; idx+=256) W[idx] = Wn_i[idx];
    __syncthreads();

    int row = blockIdx.x*256 + t;
    float hn[32];
    #pragma unroll
    for (int kk=0;kk<32;kk++) hn[kk] = fmaf(s0[kk], g_h1[row*32+kk], t0[kk]);
    float z[32];
    #pragma unroll
    for (int cc=0;cc<32;cc++) z[cc] = bsh[cc];
    #pragma unroll
    for (int kk=0;kk<32;kk++){
        float xv = hn[kk];
        #pragma unroll
        for (int cc=0;cc<32;cc++) z[cc] = fmaf(xv, W[kk*32+cc], z[cc]);
    }
    int lane = t & 31;
    #pragma unroll
    for (int cc=0;cc<32;cc++){
        float h = lrelu(z[cc]);
        g_h2[row*32+cc] = h;
        float v1 = h, v2 = h*h;
        #pragma unroll
        for (int off=16; off>0; off>>=1){
            v1 += __shfl_xor_sync(0xFFFFFFFFu, v1, off);
            v2 += __shfl_xor_sync(0xFFFFFFFFu, v2, off);
        }
        if (lane == 0){ atomicAdd(&ssum[cc], v1); atomicAdd(&sssum[cc], v2); }
    }
    __syncthreads();
    if (t < 32){
        atomicAdd(&g_sh1[t], (double)ssum[t]);
        atomicAdd(&g_ssh1[t], (double)sssum[t]);
    }
}

// ---------------- node final: update linear + tanh ---------------------
__global__ void __launch_bounds__(256) k_node2(const float* __restrict__ Wu_i,
                                               const float* __restrict__ bu_i,
                                               const float* __restrict__ gn1,
                                               const float* __restrict__ bn1v,
                                               float* __restrict__ out,
                                               int is_last){
    __shared__ float W[1024];
    __shared__ float s0[32], t0[32], bsh[32];
    int t = threadIdx.x;
    if (t < 32){
        double m = g_sh1[t]/NT_D;
        double v = g_ssh1[t]/NT_D - m*m;
        float s = gn1[t] * rsqrtf((float)v + BNEPS);
        s0[t] = s; t0[t] = bn1v[t] - (float)m*s;
        bsh[t] = bu_i[t];
    }
    for (int idx=t; idx<1024; idx+=256) W[idx] = Wu_i[idx];
    __syncthreads();

    int row = blockIdx.x*256 + t;
    float hn[32];
    #pragma unroll
    for (int kk=0;kk<32;kk++) hn[kk] = fmaf(s0[kk], g_h2[row*32+kk], t0[kk]);
    float z[32];
    #pragma unroll
    for (int cc=0;cc<32;cc++) z[cc] = bsh[cc];
    #pragma unroll
    for (int kk=0;kk<32;kk++){
        float xv = hn[kk];
        #pragma unroll
        for (int cc=0;cc<32;cc++) z[cc] = fmaf(xv, W[kk*32+cc], z[cc]);
    }
    #pragma unroll
    for (int cc=0;cc<32;cc++){
        float o = tanhf(z[cc]);
        g_x[row*32+cc] = o;
        if (is_last) out[row*32+cc] = o;
    }
}

// ----------------------------------------------------------------------
extern "C" void kernel_launch(void* const* d_in, const int* in_sizes, int n_in,
                              void* d_out, int out_size){
    const float* x    = (const float*)d_in[0];
    const float* Wah  = (const float*)d_in[1];
    const float* bah  = (const float*)d_in[2];
    const float* Wa   = (const float*)d_in[3];
    const float* ba   = (const float*)d_in[4];
    const float* geh  = (const float*)d_in[5];
    const float* beh  = (const float*)d_in[6];
    const float* ge   = (const float*)d_in[7];
    const float* be   = (const float*)d_in[8];
    const float* Wn0  = (const float*)d_in[9];
    const float* bn0  = (const float*)d_in[10];
    const float* Wn   = (const float*)d_in[11];
    const float* bnn  = (const float*)d_in[12];
    const float* gn   = (const float*)d_in[13];
    const float* bnv  = (const float*)d_in[14];
    const float* Wu   = (const float*)d_in[15];
    const float* bu   = (const float*)d_in[16];
    float* out = (float*)d_out;

    const size_t SMEM_STATS = (8192 + 4224 + 4096 + 256)*sizeof(float);        // 67072
    const size_t SMEM_MAIN  = (8192 + 8192 + 4096 + 256 + 32)*sizeof(float);   // 83072
    cudaFuncSetAttribute(k_edge_stats, cudaFuncAttributeMaxDynamicSharedMemorySize, (int)SMEM_STATS);
    cudaFuncSetAttribute(k_edge_main,  cudaFuncAttributeMaxDynamicSharedMemorySize, (int)SMEM_MAIN);

    k_pad<<<NT*HH/256, 256>>>(x);

    for (int i=0; i<4; i++){
        k_zero<<<1,128>>>();
        k_pre<<<128,256>>>(Wah + i*66*64, bah + i*64);
        k_edge_stats<<<dim3(8,64),256,SMEM_STATS>>>(Wah + i*66*64);
        k_fold1<<<1,256>>>(Wa + i*64*32, ba + i*32, geh + i*64, beh + i*64);
        k_edge_main<<<dim3(8,64),256,SMEM_MAIN>>>(Wah + i*66*64);
        k_node0<<<32,256>>>(Wn0 + i*64*32, bn0 + i*32, ge + i*32, be + i*32);
        k_node1<<<32,256>>>(Wn + i*32*32, bnn + i*32, gn + (i*2+0)*32, bnv + (i*2+0)*32);
        k_node2<<<32,256>>>(Wu + i*32*32, bu + i*32, gn + (i*2+1)*32, bnv + (i*2+1)*32,
                            out, (i==3) ? 1 : 0);
    }
}